// round 6
// baseline (speedup 1.0000x reference)
#include <cuda_runtime.h>
#include <cuda_fp16.h>
#include <math.h>

#define DIMV 2048
#define NTR  4096
#define MDEVR 8192
#define TST  500
#define ETA  0.1f
#define NTHREADS 256
#define NWARPS 8

#define S_GRAD_F   1.7179869184e10f   /* 2^34 */
#define INV_SGRAD  5.8207660913e-11f  /* 2^-34 */
#define S_DEV_F    4.294967296e9f     /* 2^32 */
#define INV_SDEV   2.3283064365e-10f  /* 2^-32 */

// Persistent device state (static allocation — no cudaMalloc anywhere)
__device__ unsigned long long g_gradacc[DIMV];  // fixed-point running totals
__device__ unsigned long long g_devacc;
__device__ unsigned           g_arrive;
__device__ __half g_xn_h[(size_t)NTR * DIMV];     // 16.8 MB
__device__ __half g_dxn_h[(size_t)MDEVR * DIMV];  // 33.6 MB

// ---------------------------------------------------------------------------
__global__ void ak_init(float* __restrict__ out, int out_size) {
    int i = blockIdx.x * blockDim.x + threadIdx.x;
    if (i == 0) { g_arrive = 0u; g_devacc = 0ull; }
    if (i < DIMV) g_gradacc[i] = 0ull;
    for (int j = TST + 1 + i; j < out_size; j += gridDim.x * blockDim.x)
        out[j] = 0.0f;
}

__global__ void ak_convert(const float* __restrict__ xn,
                           const float* __restrict__ dxn) {
    const size_t n4  = (size_t)NTR * DIMV / 4;
    const size_t m4  = (size_t)MDEVR * DIMV / 4;
    const float4* s0 = (const float4*)xn;
    const float4* s1 = (const float4*)dxn;
    __half2* d0 = (__half2*)g_xn_h;
    __half2* d1 = (__half2*)g_dxn_h;
    size_t stride = (size_t)gridDim.x * blockDim.x;
    for (size_t i = blockIdx.x * (size_t)blockDim.x + threadIdx.x; i < n4; i += stride) {
        float4 v = s0[i];
        d0[2*i+0] = __floats2half2_rn(v.x, v.y);
        d0[2*i+1] = __floats2half2_rn(v.z, v.w);
    }
    for (size_t i = blockIdx.x * (size_t)blockDim.x + threadIdx.x; i < m4; i += stride) {
        float4 v = s1[i];
        d1[2*i+0] = __floats2half2_rn(v.x, v.y);
        d1[2*i+1] = __floats2half2_rn(v.z, v.w);
    }
}

__device__ __forceinline__ void grid_barrier(unsigned nb) {
    __syncthreads();
    if (threadIdx.x == 0) {
        __threadfence();
        unsigned old = atomicAdd(&g_arrive, 1u);
        unsigned target = (old / nb + 1u) * nb;
        while (*((volatile unsigned*)&g_arrive) < target) { }
        __threadfence();
    }
    __syncthreads();
}

__device__ __forceinline__ float dev_loss_elem(float z, float y) {
    return fmaxf(z, 0.0f) - y * z + log1pf(expf(-fabsf(z)));
}

__device__ __forceinline__ void dot8h(__half2* acc2, const uint4& u, const __half2* th2j) {
    const __half2* h = (const __half2*)&u;
    acc2[0] = __hfma2(h[0], th2j[0], acc2[0]);
    acc2[1] = __hfma2(h[1], th2j[1], acc2[1]);
    acc2[2] = __hfma2(h[2], th2j[2], acc2[2]);
    acc2[3] = __hfma2(h[3], th2j[3], acc2[3]);
}

__device__ __forceinline__ void grad8h(__half2* gj, const uint4& u, __half2 ch2) {
    const __half2* h = (const __half2*)&u;
    gj[0] = __hfma2(ch2, h[0], gj[0]);
    gj[1] = __hfma2(ch2, h[1], gj[1]);
    gj[2] = __hfma2(ch2, h[2], gj[2]);
    gj[3] = __hfma2(ch2, h[3], gj[3]);
}

__device__ __forceinline__ float acc4_to_float(const __half2* a) {
    float2 f0 = __half22float2(a[0]);
    float2 f1 = __half22float2(a[1]);
    float2 f2 = __half22float2(a[2]);
    float2 f3 = __half22float2(a[3]);
    return (f0.x + f0.y) + (f1.x + f1.y) + (f2.x + f2.y) + (f3.x + f3.y);
}

// R contiguous train rows: dot + interleaved reduce + fused grad accumulation.
// After the butterfly, z[r] is identical on all lanes.
template<int R>
__device__ __forceinline__ void train_chunk(
    int n0, int lane, int t, const __half2* th2, __half2* hacc,
    const float* __restrict__ yn, const float* __restrict__ alphas)
{
    const uint4* xp[R];
#pragma unroll
    for (int r = 0; r < R; r++)
        xp[r] = (const uint4*)(g_xn_h + (size_t)(n0 + r) * DIMV);
    const __half2 hz = __float2half2_rn(0.0f);
    __half2 a[R][4];
#pragma unroll
    for (int r = 0; r < R; r++) { a[r][0]=hz; a[r][1]=hz; a[r][2]=hz; a[r][3]=hz; }
#pragma unroll
    for (int j = 0; j < 8; j++) {
#pragma unroll
        for (int r = 0; r < R; r++) {
            uint4 u = xp[r][j*32+lane];
            dot8h(a[r], u, th2 + j*4);
        }
    }
    float z[R];
#pragma unroll
    for (int r = 0; r < R; r++) z[r] = acc4_to_float(a[r]);
#pragma unroll
    for (int o = 16; o; o >>= 1) {
#pragma unroll
        for (int r = 0; r < R; r++)
            z[r] += __shfl_xor_sync(0xffffffffu, z[r], o);
    }
    __half2 ch[R];
#pragma unroll
    for (int r = 0; r < R; r++) {
        float s = 1.0f / (1.0f + expf(-z[r]));
        float c = alphas[(size_t)t * NTR + (n0 + r)] * (s - yn[n0 + r]);
        ch[r] = __float2half2_rn(c);
    }
#pragma unroll
    for (int j = 0; j < 8; j++) {
#pragma unroll
        for (int r = 0; r < R; r++) {
            uint4 u = xp[r][j*32+lane];   // L1 hits
            grad8h(hacc + j*4, u, ch[r]);
        }
    }
}

// R contiguous dev rows. Returns the FULL loss sum of the R rows, identical
// on all lanes (z[r] is fully warp-reduced) — caller must NOT reduce again.
template<int R>
__device__ __forceinline__ float dev_chunk(
    int m0, int lane, const __half2* th2, const float* __restrict__ dyn)
{
    const uint4* xp[R];
#pragma unroll
    for (int r = 0; r < R; r++)
        xp[r] = (const uint4*)(g_dxn_h + (size_t)(m0 + r) * DIMV);
    const __half2 hz = __float2half2_rn(0.0f);
    __half2 a[R][4];
#pragma unroll
    for (int r = 0; r < R; r++) { a[r][0]=hz; a[r][1]=hz; a[r][2]=hz; a[r][3]=hz; }
#pragma unroll
    for (int j = 0; j < 8; j++) {
#pragma unroll
        for (int r = 0; r < R; r++) {
            uint4 u = xp[r][j*32+lane];
            dot8h(a[r], u, th2 + j*4);
        }
    }
    float z[R];
#pragma unroll
    for (int r = 0; r < R; r++) z[r] = acc4_to_float(a[r]);
#pragma unroll
    for (int o = 16; o; o >>= 1) {
#pragma unroll
        for (int r = 0; r < R; r++)
            z[r] += __shfl_xor_sync(0xffffffffu, z[r], o);
    }
    float s = 0.0f;
#pragma unroll
    for (int r = 0; r < R; r++) s += dev_loss_elem(z[r], dyn[m0 + r]);
    return s;
}

// ---------------------------------------------------------------------------
__global__ void __launch_bounds__(NTHREADS, 1)
ak_train(const float* __restrict__ theta0,
         const float* __restrict__ yn,  const float* __restrict__ dyn,
         const float* __restrict__ alphas,
         float* __restrict__ out, int out_size) {
    extern __shared__ char smc[];
    float*  s_theta = (float*)smc;                              // DIMV fp32 (8KB)
    __half* s_grad  = (__half*)(smc + DIMV * 4);                // NWARPS*DIMV (32KB)
    float*  s_dev   = (float*)(smc + DIMV * 4 + NWARPS * DIMV * 2);

    const int tid  = threadIdx.x;
    const int lane = tid & 31;
    const int w    = tid >> 5;
    const int cta  = blockIdx.x;
    const int ncta = gridDim.x;

    // CTA-blocked row ranges
    const int rb = (int)(((long long)cta * NTR) / ncta);
    const int re = (int)(((long long)(cta + 1) * NTR) / ncta);
    const int mb = (int)(((long long)cta * MDEVR) / ncta);
    const int me = (int)(((long long)(cta + 1) * MDEVR) / ncta);
    // per-warp exact sub-ranges (imbalance <= 1 row)
    const int twb = rb + (int)(((long long)(re - rb) * w) / NWARPS);
    const int twe = rb + (int)(((long long)(re - rb) * (w + 1)) / NWARPS);
    const int dwb = mb + (int)(((long long)(me - mb) * w) / NWARPS);
    const int dwe = mb + (int)(((long long)(me - mb) * (w + 1)) / NWARPS);

    for (int d = tid; d < DIMV; d += NTHREADS) s_theta[d] = theta0[d];
    __syncthreads();

    long long prev[8];
#pragma unroll
    for (int i = 0; i < 8; i++) prev[i] = 0ll;
    long long devprev = 0ll;
    float isum = 0.0f;   // cta0/tid0 only

    __half2 th2[32];
    const __half2 hz = __float2half2_rn(0.0f);

    for (int t = 0; t < TST; ++t) {
        // ---- theta(smem fp32) -> th2 registers
        {
            const float4* t4 = (const float4*)s_theta;
#pragma unroll
            for (int j = 0; j < 8; j++) {
                float4 v0 = t4[(j*32+lane)*2 + 0];
                float4 v1 = t4[(j*32+lane)*2 + 1];
                th2[j*4+0] = __floats2half2_rn(v0.x, v0.y);
                th2[j*4+1] = __floats2half2_rn(v0.z, v0.w);
                th2[j*4+2] = __floats2half2_rn(v1.x, v1.y);
                th2[j*4+3] = __floats2half2_rn(v1.z, v1.w);
            }
        }

        // ---- train rows (quad -> pair -> single)
        __half2 hacc[32];
#pragma unroll
        for (int j = 0; j < 32; j++) hacc[j] = hz;
        {
            int n = twb;
            for (; n + 4 <= twe; n += 4) train_chunk<4>(n, lane, t, th2, hacc, yn, alphas);
            if (n + 2 <= twe) { train_chunk<2>(n, lane, t, th2, hacc, yn, alphas); n += 2; }
            if (n < twe)        train_chunk<1>(n, lane, t, th2, hacc, yn, alphas);
        }
        // per-warp grad -> smem (half2)
        {
            uint4* gp4 = (uint4*)(s_grad + (size_t)w * DIMV);
#pragma unroll
            for (int j = 0; j < 8; j++) {
                uint4 u;
                ((__half2*)&u)[0] = hacc[j*4+0];
                ((__half2*)&u)[1] = hacc[j*4+1];
                ((__half2*)&u)[2] = hacc[j*4+2];
                ((__half2*)&u)[3] = hacc[j*4+3];
                gp4[j*32+lane] = u;
            }
        }

        // ---- dev loss with theta_t (= full_losses[t]); dsum is identical
        //      on all lanes (dev_chunk returns fully-reduced sums)
        float dsum = 0.0f;
        {
            int m = dwb;
            for (; m + 4 <= dwe; m += 4) dsum += dev_chunk<4>(m, lane, th2, dyn);
            if (m + 2 <= dwe) { dsum += dev_chunk<2>(m, lane, th2, dyn); m += 2; }
            if (m < dwe)        dsum += dev_chunk<1>(m, lane, th2, dyn);
        }
        if (lane == 0) s_dev[w] = dsum;   // NO further reduction (already full)
        __syncthreads();

        // ---- CTA reduce + fixed-point atomics into running totals
        if (tid == 0) {
            float s = 0.0f;
#pragma unroll
            for (int i = 0; i < NWARPS; i++) s += s_dev[i];
            atomicAdd(&g_devacc, (unsigned long long)llrintf(s * S_DEV_F));
        }
        {
            const __half2* sg2 = (const __half2*)s_grad;
#pragma unroll
            for (int i = 0; i < 4; i++) {          // (DIMV/2)/NTHREADS = 4
                int idx = tid + i * NTHREADS;
                float2 s = make_float2(0.0f, 0.0f);
#pragma unroll
                for (int ww = 0; ww < NWARPS; ww++) {
                    float2 f = __half22float2(sg2[ww * (DIMV/2) + idx]);
                    s.x += f.x; s.y += f.y;
                }
                atomicAdd(&g_gradacc[2*idx+0], (unsigned long long)llrintf(s.x * S_GRAD_F));
                atomicAdd(&g_gradacc[2*idx+1], (unsigned long long)llrintf(s.y * S_GRAD_F));
            }
        }

        grid_barrier((unsigned)ncta);

        // ---- apply delta: every CTA updates its own smem theta identically
        {
            const long long* ga = (const long long*)g_gradacc;
#pragma unroll
            for (int i = 0; i < 8; i++) {
                int d = tid * 8 + i;
                long long v = ga[d];
                float g = (float)(v - prev[i]) * INV_SGRAD;
                prev[i] = v;
                s_theta[d] -= ETA * g;
            }
            if (cta == 0 && tid == 0) {
                long long dv = (long long)g_devacc;
                float Lt = (float)(dv - devprev) * INV_SDEV * (1.0f / MDEVR);
                devprev = dv;
                if (1 + t < out_size) out[1 + t] = Lt;
                if (t >= 1) isum += Lt;
            }
        }
        __syncthreads();
    }

    // ---- final dev eval at theta_T; finalize scalar loss
    {
        const float4* t4 = (const float4*)s_theta;
#pragma unroll
        for (int j = 0; j < 8; j++) {
            float4 v0 = t4[(j*32+lane)*2 + 0];
            float4 v1 = t4[(j*32+lane)*2 + 1];
            th2[j*4+0] = __floats2half2_rn(v0.x, v0.y);
            th2[j*4+1] = __floats2half2_rn(v0.z, v0.w);
            th2[j*4+2] = __floats2half2_rn(v1.x, v1.y);
            th2[j*4+3] = __floats2half2_rn(v1.z, v1.w);
        }
        float dsum = 0.0f;
        {
            int m = dwb;
            for (; m + 4 <= dwe; m += 4) dsum += dev_chunk<4>(m, lane, th2, dyn);
            if (m + 2 <= dwe) { dsum += dev_chunk<2>(m, lane, th2, dyn); m += 2; }
            if (m < dwe)        dsum += dev_chunk<1>(m, lane, th2, dyn);
        }
        if (lane == 0) s_dev[w] = dsum;   // already fully reduced
        __syncthreads();
        if (tid == 0) {
            float s = 0.0f;
#pragma unroll
            for (int i = 0; i < NWARPS; i++) s += s_dev[i];
            atomicAdd(&g_devacc, (unsigned long long)llrintf(s * S_DEV_F));
        }
        grid_barrier((unsigned)ncta);
        if (cta == 0 && tid == 0) {
            long long dv = (long long)g_devacc;
            float LT = (float)(dv - devprev) * INV_SDEV * (1.0f / MDEVR);
            if (out_size > 0) out[0] = (isum + LT) / (float)TST;
        }
    }
}

// ---------------------------------------------------------------------------
extern "C" void kernel_launch(void* const* d_in, const int* in_sizes, int n_in,
                              void* d_out, int out_size) {
    const float *theta = nullptr, *alphas = nullptr, *xn = nullptr,
                *yn = nullptr, *dxn = nullptr, *dyn = nullptr;
    for (int i = 0; i < n_in; i++) {
        switch (in_sizes[i]) {
            case DIMV:         theta  = (const float*)d_in[i]; break;
            case TST * NTR:    alphas = (const float*)d_in[i]; break;
            case NTR * DIMV:   xn     = (const float*)d_in[i]; break;
            case NTR:          yn     = (const float*)d_in[i]; break;
            case MDEVR * DIMV: dxn    = (const float*)d_in[i]; break;
            case MDEVR:        dyn    = (const float*)d_in[i]; break;
            default: break;
        }
    }
    float* out = (float*)d_out;

    int dev = 0;
    cudaGetDevice(&dev);
    int nsm = 148;
    cudaDeviceGetAttribute(&nsm, cudaDevAttrMultiProcessorCount, dev);
    int ncta = nsm < 1 ? 1 : nsm;

    size_t smem = (size_t)DIMV * 4 + (size_t)NWARPS * DIMV * 2
                + NWARPS * sizeof(float);                       // ~41KB
    cudaFuncSetAttribute(ak_train, cudaFuncAttributeMaxDynamicSharedMemorySize,
                         (int)smem);

    ak_init<<<(DIMV + 255) / 256, 256>>>(out, out_size);
    ak_convert<<<4 * nsm, 256>>>(xn, dxn);
    ak_train<<<ncta, NTHREADS, smem>>>(theta, yn, dyn, alphas, out, out_size);
}